// round 1
// baseline (speedup 1.0000x reference)
#include <cuda_runtime.h>
#include <cuda_bf16.h>

// Problem: emb = (mask @ mlp_out) / max(counts,1)
//   mlp_out = relu(idx@W1 + b1) @ W2 + b2  over scene indices 0..S-1
// Factorized: emb = ((mask @ h) @ W2 + counts*b2) / max(counts,1)
//   where h = relu(idx@W1+b1) is [S,16]  -> per-row accumulation is 16-dim.
//
// Kernel 1: build h table [S,16] into __device__ scratch.
// Kernel 2: persistent blocks, h table in smem (stride 17 to spread banks),
//           warp-per-row: float4 scan + ballot nonzero extraction, two
//           nonzeros processed per iteration (half-warp each, 16 lanes = 16 dims),
//           epilogue computes 128-dim output via W2 in smem.

#define S        2000
#define SV4      500           // S/4 float4 per row
#define NGROUPS  16            // ceil(SV4/32)
#define HDIM     16
#define HSTRIDE  17            // padded row stride in smem (bank spread)
#define EDIM     128
#define WARPS    16
#define THREADS  512

__device__ float g_h[S * HDIM];

__global__ void build_h_kernel(const float* __restrict__ W1,
                               const float* __restrict__ b1) {
    int i = blockIdx.x * blockDim.x + threadIdx.x;
    if (i < S * HDIM) {
        int s = i >> 4;
        int d = i & 15;
        float v = fmaf((float)s, W1[d], b1[d]);
        g_h[i] = v > 0.0f ? v : 0.0f;
    }
}

__global__ void __launch_bounds__(THREADS, 1)
embed_kernel(const float* __restrict__ m,
             const float* __restrict__ W2,
             const float* __restrict__ b2,
             float* __restrict__ out,
             int L) {
    extern __shared__ float sm[];
    float* hs  = sm;                        // S * HSTRIDE
    float* w2s = sm + S * HSTRIDE;          // HDIM * EDIM
    float* b2s = w2s + HDIM * EDIM;         // EDIM

    // Load tables once per (persistent) block.
    for (int i = threadIdx.x; i < S * HDIM; i += THREADS) {
        int s = i >> 4, d = i & 15;
        hs[s * HSTRIDE + d] = g_h[i];
    }
    for (int i = threadIdx.x; i < HDIM * EDIM; i += THREADS) w2s[i] = W2[i];
    for (int i = threadIdx.x; i < EDIM; i += THREADS) b2s[i] = b2[i];
    __syncthreads();

    const int wid  = threadIdx.x >> 5;
    const int lane = threadIdx.x & 31;
    const int half = lane >> 4;      // 0: even nz, 1: odd nz
    const int d    = lane & 15;      // dim owned by this lane
    const int warpsTotal = gridDim.x * WARPS;

    for (int row = blockIdx.x * WARPS + wid; row < L; row += warpsTotal) {
        const float4* row4 = reinterpret_cast<const float4*>(m + (size_t)row * S);
        float acc = 0.0f;
        int count = 0;

        #pragma unroll
        for (int g0 = 0; g0 < NGROUPS; g0 += 4) {
            float4 v[4];
            #pragma unroll
            for (int u = 0; u < 4; u++) {
                int idx = (g0 + u) * 32 + lane;
                v[u] = (idx < SV4) ? __ldg(&row4[idx])
                                   : make_float4(0.f, 0.f, 0.f, 0.f);
            }
            #pragma unroll
            for (int u = 0; u < 4; u++) {
                const int base = (g0 + u) * 128;   // scene of bit p, elem e: base + 4p + e
                unsigned bx = __ballot_sync(0xffffffffu, v[u].x != 0.0f);
                unsigned by = __ballot_sync(0xffffffffu, v[u].y != 0.0f);
                unsigned bz = __ballot_sync(0xffffffffu, v[u].z != 0.0f);
                unsigned bw = __ballot_sync(0xffffffffu, v[u].w != 0.0f);
                count += __popc(bx) + __popc(by) + __popc(bz) + __popc(bw);

                #pragma unroll
                for (int e = 0; e < 4; e++) {
                    unsigned b = (e == 0) ? bx : (e == 1) ? by : (e == 2) ? bz : bw;
                    int n = __popc(b);
                    // two nonzeros per iteration: half-warp 0 takes even i,
                    // half-warp 1 takes odd i; 16 lanes cover the 16 dims.
                    int a17 = base * HSTRIDE + e * HSTRIDE + d; // (base+e)*17+d... careful below
                    // NOTE: scene = base + 4p + e -> addr = (base+e)*17 ... wrong:
                    // addr = (base + 4p + e)*HSTRIDE + d. Precompute constant part:
                    a17 = (base + e) * HSTRIDE + d;
                    for (int i = half; i < n; i += 2) {
                        int p = (int)__fns(b, 0, i + 1);
                        acc += hs[a17 + p * (4 * HSTRIDE)];
                    }
                }
            }
        }

        // Reduce the two halves: lane l now holds total for dim (l&15).
        acc += __shfl_xor_sync(0xffffffffu, acc, 16);

        // Broadcast the 16 totals to all lanes.
        float a[HDIM];
        #pragma unroll
        for (int dd = 0; dd < HDIM; dd++)
            a[dd] = __shfl_sync(0xffffffffu, acc, dd);

        float cnt = (float)count;
        float inv = 1.0f / fmaxf(cnt, 1.0f);
        float* o = out + (size_t)row * EDIM;

        #pragma unroll
        for (int k = 0; k < 4; k++) {
            int c = lane + k * 32;
            float sum = cnt * b2s[c];
            #pragma unroll
            for (int dd = 0; dd < HDIM; dd++)
                sum = fmaf(a[dd], w2s[dd * EDIM + c], sum);
            o[c] = sum * inv;
        }
    }
}

extern "C" void kernel_launch(void* const* d_in, const int* in_sizes, int n_in,
                              void* d_out, int out_size) {
    const float* m  = (const float*)d_in[0];
    const float* W1 = (const float*)d_in[1];
    const float* b1 = (const float*)d_in[2];
    const float* W2 = (const float*)d_in[3];
    const float* b2 = (const float*)d_in[4];
    float* out = (float*)d_out;

    int L = in_sizes[0] / S;

    build_h_kernel<<<(S * HDIM + 255) / 256, 256>>>(W1, b1);

    size_t smem = (size_t)(S * HSTRIDE + HDIM * EDIM + EDIM) * sizeof(float);
    cudaFuncSetAttribute(embed_kernel,
                         cudaFuncAttributeMaxDynamicSharedMemorySize, (int)smem);

    int dev = 0, sms = 148;
    cudaGetDevice(&dev);
    cudaDeviceGetAttribute(&sms, cudaDevAttrMultiProcessorCount, dev);

    embed_kernel<<<sms, THREADS, smem>>>(m, W2, b2, out, L);
}

// round 2
// speedup vs baseline: 44.4075x; 44.4075x over previous
#include <cuda_runtime.h>
#include <cuda_bf16.h>

// emb = ((mask @ h) @ W2 + counts*b2) / max(counts,1),  h = relu(idx@W1+b1) [S,16]
//
// Kernel 1: build h table [S,16].
// Kernel 2: warp-per-row. Stream the row as float4, ballot per component to get
//           nonzero bitmasks (warp-uniform), extract bits with __ffs + clear
//           (NO __fns — it is software-emulated on sm_10x). Four nonzeros are
//           serviced per iteration: lanes are split into 4 groups of 8, each
//           group loads one scene's h row as float2 (2 dims/lane) from smem.
//           Epilogue: reduce across groups, expand 16 dims -> 128 via W2 smem.

#define S        2000
#define SV4      500            // S/4 float4 per row
#define NGROUPS  16             // ceil(SV4/32)
#define HDIM     16
#define HSTRIDE  18             // even (float2-aligned), spreads banks
#define EDIM     128
#define THREADS  1024
#define WARPS    32

__device__ float g_h[S * HDIM];

__global__ void build_h_kernel(const float* __restrict__ W1,
                               const float* __restrict__ b1) {
    int i = blockIdx.x * blockDim.x + threadIdx.x;
    if (i < S * HDIM) {
        int s = i >> 4;
        int d = i & 15;
        float v = fmaf((float)s, W1[d], b1[d]);
        g_h[i] = v > 0.0f ? v : 0.0f;
    }
}

__global__ void __launch_bounds__(THREADS, 1)
embed_kernel(const float* __restrict__ m,
             const float* __restrict__ W2,
             const float* __restrict__ b2,
             float* __restrict__ out,
             int L) {
    extern __shared__ float sm[];
    float* hs  = sm;                        // S * HSTRIDE
    float* w2s = sm + S * HSTRIDE;          // HDIM * EDIM
    float* b2s = w2s + HDIM * EDIM;         // EDIM

    for (int i = threadIdx.x; i < S * HDIM; i += THREADS) {
        int s = i >> 4, d = i & 15;
        hs[s * HSTRIDE + d] = g_h[i];
    }
    for (int i = threadIdx.x; i < HDIM * EDIM; i += THREADS) w2s[i] = W2[i];
    for (int i = threadIdx.x; i < EDIM; i += THREADS) b2s[i] = b2[i];
    __syncthreads();

    const int wid  = threadIdx.x >> 5;
    const int lane = threadIdx.x & 31;
    const int q    = lane >> 3;        // which extracted nonzero (0..3)
    const int d2   = lane & 7;         // dim pair owned by this lane
    const int warpsTotal = gridDim.x * WARPS;

    for (int row = blockIdx.x * WARPS + wid; row < L; row += warpsTotal) {
        const float4* row4 = reinterpret_cast<const float4*>(m + (size_t)row * S);
        float ax = 0.0f, ay = 0.0f;
        int count = 0;

        float4 vcur = __ldg(&row4[lane]);   // group 0: idx = lane < 500 always

        for (int g = 0; g < NGROUPS; g++) {
            float4 vnext = make_float4(0.f, 0.f, 0.f, 0.f);
            if (g + 1 < NGROUPS) {
                int idx = (g + 1) * 32 + lane;
                if (idx < SV4) vnext = __ldg(&row4[idx]);
            }

            unsigned bb0 = __ballot_sync(0xffffffffu, vcur.x != 0.0f);
            unsigned bb1 = __ballot_sync(0xffffffffu, vcur.y != 0.0f);
            unsigned bb2 = __ballot_sync(0xffffffffu, vcur.z != 0.0f);
            unsigned bb3 = __ballot_sync(0xffffffffu, vcur.w != 0.0f);
            count += __popc(bb0) + __popc(bb1) + __popc(bb2) + __popc(bb3);

            const int base = g * 128;       // scene = base + 4*p + e

            #pragma unroll
            for (int e = 0; e < 4; e++) {
                unsigned b = (e == 0) ? bb0 : (e == 1) ? bb1 : (e == 2) ? bb2 : bb3;
                while (b) {
                    // extract up to 4 set bits (warp-uniform values)
                    int p0 = __ffs(b) - 1; b &= b - 1;
                    int p1 = __ffs(b) - 1; b &= b - 1;
                    int p2 = __ffs(b) - 1; b &= b - 1;
                    int p3 = __ffs(b) - 1; b &= b - 1;
                    int p  = (q == 0) ? p0 : (q == 1) ? p1 : (q == 2) ? p2 : p3;
                    if (p >= 0) {
                        int scene = base + 4 * p + e;
                        const float2 hv = *reinterpret_cast<const float2*>(
                            &hs[scene * HSTRIDE + 2 * d2]);
                        ax += hv.x;
                        ay += hv.y;
                    }
                }
            }
            vcur = vnext;
        }

        // reduce the 4 lane-groups: dims live on lanes 0..7 afterwards
        ax += __shfl_xor_sync(0xffffffffu, ax, 8);
        ay += __shfl_xor_sync(0xffffffffu, ay, 8);
        ax += __shfl_xor_sync(0xffffffffu, ax, 16);
        ay += __shfl_xor_sync(0xffffffffu, ay, 16);

        // broadcast 16 dim totals to all lanes
        float a[HDIM];
        #pragma unroll
        for (int k = 0; k < 8; k++) {
            a[2 * k]     = __shfl_sync(0xffffffffu, ax, k);
            a[2 * k + 1] = __shfl_sync(0xffffffffu, ay, k);
        }

        float cnt = (float)count;
        float inv = 1.0f / fmaxf(cnt, 1.0f);
        float* o = out + (size_t)row * EDIM;

        #pragma unroll
        for (int k = 0; k < 4; k++) {
            int c = lane + k * 32;
            float sum = cnt * b2s[c];
            #pragma unroll
            for (int dd = 0; dd < HDIM; dd++)
                sum = fmaf(a[dd], w2s[dd * EDIM + c], sum);
            o[c] = sum * inv;
        }
    }
}

extern "C" void kernel_launch(void* const* d_in, const int* in_sizes, int n_in,
                              void* d_out, int out_size) {
    const float* m  = (const float*)d_in[0];
    const float* W1 = (const float*)d_in[1];
    const float* b1 = (const float*)d_in[2];
    const float* W2 = (const float*)d_in[3];
    const float* b2 = (const float*)d_in[4];
    float* out = (float*)d_out;

    int L = in_sizes[0] / S;

    build_h_kernel<<<(S * HDIM + 255) / 256, 256>>>(W1, b1);

    size_t smem = (size_t)(S * HSTRIDE + HDIM * EDIM + EDIM) * sizeof(float);
    cudaFuncSetAttribute(embed_kernel,
                         cudaFuncAttributeMaxDynamicSharedMemorySize, (int)smem);

    int dev = 0, sms = 148;
    cudaGetDevice(&dev);
    cudaDeviceGetAttribute(&sms, cudaDevAttrMultiProcessorCount, dev);

    embed_kernel<<<sms, THREADS, smem>>>(m, W2, b2, out, L);
}

// round 3
// speedup vs baseline: 114.9476x; 2.5885x over previous
#include <cuda_runtime.h>
#include <cuda_bf16.h>

// emb = ((mask @ h) @ W2 + counts*b2) / max(counts,1),  h = relu(idx@W1+b1) [S,16]
//
// Warp-per-row, two-stage:
//   compact: ballot + prefix-popc writes nonzero scene indices to a per-warp
//            smem buffer (no __ffs/__fns, no data-dependent while loop)
//   consume: dense loop over the index list; 4 lane-groups of 8 each service
//            one index per iteration (broadcast LDS idx + LDS.64 of h row).
// Row processed in 4 chunks of 512 scenes so the 512-entry buffer can't overflow.

#define S        2000
#define SV4      500            // S/4 float4 per row
#define HDIM     16
#define HSTRIDE  18             // even (float2-aligned), spreads banks
#define EDIM     128
#define THREADS  1024
#define WARPS    32
#define CAP      512            // index buffer entries per warp

__device__ float g_h[S * HDIM];

__global__ void build_h_kernel(const float* __restrict__ W1,
                               const float* __restrict__ b1) {
    int i = blockIdx.x * blockDim.x + threadIdx.x;
    if (i < S * HDIM) {
        int s = i >> 4;
        int d = i & 15;
        float v = fmaf((float)s, W1[d], b1[d]);
        g_h[i] = v > 0.0f ? v : 0.0f;
    }
}

__global__ void __launch_bounds__(THREADS, 1)
embed_kernel(const float* __restrict__ m,
             const float* __restrict__ W2,
             const float* __restrict__ b2,
             float* __restrict__ out,
             int L) {
    extern __shared__ float sm[];
    float* hs  = sm;                              // S * HSTRIDE
    float* w2s = sm + S * HSTRIDE;                // HDIM * EDIM
    float* b2s = w2s + HDIM * EDIM;               // EDIM
    unsigned* sidx_all = (unsigned*)(b2s + EDIM); // WARPS * CAP

    for (int i = threadIdx.x; i < S * HDIM; i += THREADS) {
        int s = i >> 4, d = i & 15;
        hs[s * HSTRIDE + d] = g_h[i];
    }
    for (int i = threadIdx.x; i < HDIM * EDIM; i += THREADS) w2s[i] = W2[i];
    for (int i = threadIdx.x; i < EDIM; i += THREADS) b2s[i] = b2[i];
    __syncthreads();

    const int wid  = threadIdx.x >> 5;
    const int lane = threadIdx.x & 31;
    const int q    = lane >> 3;        // lane-group: which index to service
    const int d2   = lane & 7;         // dim pair owned within group
    const unsigned ltm = (1u << lane) - 1u;
    unsigned* sidx = sidx_all + wid * CAP;
    const int warpsTotal = gridDim.x * WARPS;

    for (int row = blockIdx.x * WARPS + wid; row < L; row += warpsTotal) {
        const float4* row4 = reinterpret_cast<const float4*>(m + (size_t)row * S);
        float ax = 0.0f, ay = 0.0f;
        int count = 0;

        float4 vcur = __ldg(&row4[lane]);   // group 0 always in-range

        #pragma unroll
        for (int c = 0; c < 4; c++) {       // 4 chunks x 512 scenes
            int cnt = 0;
            #pragma unroll
            for (int u = 0; u < 4; u++) {   // 4 float4-groups per chunk
                const int g = c * 4 + u;
                float4 v = vcur;
                // prefetch next group (lands during this chunk's consume)
                if (g + 1 < 16) {
                    int nidx = (g + 1) * 32 + lane;
                    float4 vn = make_float4(0.f, 0.f, 0.f, 0.f);
                    if (nidx < SV4) vn = __ldg(&row4[nidx]);
                    vcur = vn;
                }
                const int sbase = g * 128 + 4 * lane;
                #pragma unroll
                for (int e = 0; e < 4; e++) {
                    float comp = (e == 0) ? v.x : (e == 1) ? v.y
                               : (e == 2) ? v.z : v.w;
                    bool nz = (comp != 0.0f);
                    unsigned be = __ballot_sync(0xffffffffu, nz);
                    if (nz) sidx[cnt + __popc(be & ltm)] = sbase + e;
                    cnt += __popc(be);
                }
            }
            count += cnt;
            __syncwarp();
            // consume: 4 indices per iteration (one per lane-group)
            for (int i = q; i < cnt; i += 4) {
                unsigned scene = sidx[i];
                const float2 hv = *reinterpret_cast<const float2*>(
                    &hs[scene * HSTRIDE + 2 * d2]);
                ax += hv.x;
                ay += hv.y;
            }
            __syncwarp();
        }

        // reduce across the 4 lane-groups: dims land on lanes 0..7
        ax += __shfl_xor_sync(0xffffffffu, ax, 8);
        ay += __shfl_xor_sync(0xffffffffu, ay, 8);
        ax += __shfl_xor_sync(0xffffffffu, ax, 16);
        ay += __shfl_xor_sync(0xffffffffu, ay, 16);

        float a[HDIM];
        #pragma unroll
        for (int k = 0; k < 8; k++) {
            a[2 * k]     = __shfl_sync(0xffffffffu, ax, k);
            a[2 * k + 1] = __shfl_sync(0xffffffffu, ay, k);
        }

        float cnt_f = (float)count;
        float inv = 1.0f / fmaxf(cnt_f, 1.0f);
        float* o = out + (size_t)row * EDIM;

        #pragma unroll
        for (int k = 0; k < 4; k++) {
            int cc = lane + k * 32;
            float sum = cnt_f * b2s[cc];
            #pragma unroll
            for (int dd = 0; dd < HDIM; dd++)
                sum = fmaf(a[dd], w2s[dd * EDIM + cc], sum);
            o[cc] = sum * inv;
        }
    }
}

extern "C" void kernel_launch(void* const* d_in, const int* in_sizes, int n_in,
                              void* d_out, int out_size) {
    const float* m  = (const float*)d_in[0];
    const float* W1 = (const float*)d_in[1];
    const float* b1 = (const float*)d_in[2];
    const float* W2 = (const float*)d_in[3];
    const float* b2 = (const float*)d_in[4];
    float* out = (float*)d_out;

    int L = in_sizes[0] / S;

    build_h_kernel<<<(S * HDIM + 255) / 256, 256>>>(W1, b1);

    size_t smem = (size_t)(S * HSTRIDE + HDIM * EDIM + EDIM) * sizeof(float)
                + (size_t)WARPS * CAP * sizeof(unsigned);
    cudaFuncSetAttribute(embed_kernel,
                         cudaFuncAttributeMaxDynamicSharedMemorySize, (int)smem);

    int dev = 0, sms = 148;
    cudaGetDevice(&dev);
    cudaDeviceGetAttribute(&sms, cudaDevAttrMultiProcessorCount, dev);

    embed_kernel<<<sms, THREADS, smem>>>(m, W2, b2, out, L);
}